// round 10
// baseline (speedup 1.0000x reference)
#include <cuda_runtime.h>
#include <math.h>

typedef unsigned long long u64;
typedef ulonglong2 u64x2;

#define F_TOL_F 1e-6f
#define NBLK 128
#define SOLVER_SMEM 210496

// ---------------- device-global scratch (no allocations allowed) ------------
__device__ float g_h1[1024 * 1024];
__device__ float g_h2[1024 * 1024];
__device__ float g_W2T[1024 * 256];
__device__ float g_WzT[256 * 256];
__device__ float g_AT[256 * 128];
__device__ float g_biasproj[256];
__device__ unsigned g_res_arr[20];
__device__ unsigned g_solver_done;

// ---------------- packed fp32x2 (Blackwell double-rate fp32) ----------------
#define FFMA2(acc, a, b) \
    asm("fma.rn.f32x2 %0, %1, %2, %0;" : "+l"(acc) : "l"(a), "l"(b))
#define ADD2(acc, a) \
    asm("add.rn.f32x2 %0, %1, %0;" : "+l"(acc) : "l"(a))

__device__ __forceinline__ float2 unpack2(u64 v) {
    float2 p;
    asm("mov.b64 {%0,%1}, %2;" : "=f"(p.x), "=f"(p.y) : "l"(v));
    return p;
}
__device__ __forceinline__ u64 pack2(float lo, float hi) {
    u64 r;
    asm("mov.b64 %0, {%1,%2};" : "=l"(r) : "f"(lo), "f"(hi));
    return r;
}
__device__ __forceinline__ u64 swp(u64 v) {
    float2 f = unpack2(v);
    return pack2(f.y, f.x);
}

// ---------------- fused prep: 3 transposes + biasproj + state reset ---------
__global__ void prep_kernel(const float* __restrict__ W2,
                            const float* __restrict__ Wz,
                            const float* __restrict__ Am,
                            const float* __restrict__ bvec,
                            const float* __restrict__ WbP) {
    __shared__ float tb[32][33];
    const int b = blockIdx.x;
    const int t = threadIdx.x;
    const int tx = t & 31, ty = t >> 5;

    const float* in;
    float* out;
    int R, C, bx, by;
    if (b < 256) {
        in = W2; out = g_W2T; R = 256; C = 1024; bx = b & 31; by = b >> 5;
    } else if (b < 320) {
        int bb = b - 256;
        in = Wz; out = g_WzT; R = 256; C = 256; bx = bb & 7; by = bb >> 3;
    } else if (b < 352) {
        int bb = b - 320;
        in = Am; out = g_AT; R = 128; C = 256; bx = bb & 7; by = bb >> 3;
    } else {
        if (t < 20) g_res_arr[t] = 0u;
        if (t == 32) g_solver_done = 0u;
        if (t >= 256 && t < 512) {
            int j = t - 256;
            float s = 0.f;
#pragma unroll 8
            for (int i = 0; i < 128; i++) s += bvec[i] * WbP[j * 128 + i];
            g_biasproj[j] = s;
        }
        return;
    }
    int c = bx * 32 + tx, r = by * 32 + ty;
    tb[ty][tx] = in[r * C + c];
    __syncthreads();
    int oc = by * 32 + tx;
    int orr = bx * 32 + ty;
    out[orr * R + oc] = tb[tx][ty];
}

// ---------------- FFMA2 SGEMM: C = relu(A @ B^T + bias) ----------------------
// BM=128, BN=64, BK=16, 512 threads (4 warps/SMSP), grid (N/64, M/128).
// Thread tile 4x4: row-pair packed accs + w-swap. 2 LDS.128 : 8 FFMA2 per k.
__global__ __launch_bounds__(512, 1) void gemm_relu_f2(
    const float* __restrict__ A, const float* __restrict__ B,
    const float* __restrict__ bias, float* __restrict__ C,
    int M, int N, int K) {
    __shared__ __align__(16) float As[2][16][128];
    __shared__ __align__(16) float Bs[2][16][64];

    const int t = threadIdx.x;
    const int tx = t & 15, ty = t >> 4;  // tx: 16 col-groups, ty: 32 row-groups
    const int rowBase = blockIdx.y * 128;
    const int colBase = blockIdx.x * 64;
    const int c0 = 4 * tx, r0 = 4 * ty;

    const int rA = t >> 2, ksegA = (t & 3) * 4;   // A: 128 rows x 4k (float4)
    const int rB = t >> 3, ksegB = (t & 7) * 2;   // B: 64 rows x 2k (float2)

    const float* Aload = A + (rowBase + rA) * K + ksegA;
    const float* Bload = B + (colBase + rB) * K + ksegB;

    u64 ad[2][2], ax[2][2];
#pragma unroll
    for (int rp = 0; rp < 2; rp++)
#pragma unroll
        for (int cp = 0; cp < 2; cp++) ad[rp][cp] = ax[rp][cp] = 0ull;

    {
        float4 a1 = *(const float4*)(Aload);
        float2 bv = *(const float2*)(Bload);
#pragma unroll
        for (int j = 0; j < 4; j++) As[0][ksegA + j][rA] = ((const float*)&a1)[j];
        Bs[0][ksegB + 0][rB] = bv.x;
        Bs[0][ksegB + 1][rB] = bv.y;
    }
    __syncthreads();

    const int nt = K >> 4;
    for (int tt = 0; tt < nt; tt++) {
        const int buf = tt & 1;
        float4 a1;
        float2 bv;
        if (tt + 1 < nt) {
            a1 = *(const float4*)(Aload + (tt + 1) * 16);
            bv = *(const float2*)(Bload + (tt + 1) * 16);
        }
#pragma unroll
        for (int k = 0; k < 16; k++) {
            u64x2 za = *(const u64x2*)&As[buf][k][r0];
            u64x2 wv = *(const u64x2*)&Bs[buf][k][c0];
            u64 zp[2] = {za.x, za.y};
            u64 wp[2] = {wv.x, wv.y};
#pragma unroll
            for (int cp = 0; cp < 2; cp++) {
                u64 ws = swp(wp[cp]);
#pragma unroll
                for (int rp = 0; rp < 2; rp++) {
                    FFMA2(ad[rp][cp], zp[rp], wp[cp]);
                    FFMA2(ax[rp][cp], zp[rp], ws);
                }
            }
        }
        if (tt + 1 < nt) {
            const int nb = buf ^ 1;
#pragma unroll
            for (int j = 0; j < 4; j++)
                As[nb][ksegA + j][rA] = ((const float*)&a1)[j];
            Bs[nb][ksegB + 0][rB] = bv.x;
            Bs[nb][ksegB + 1][rB] = bv.y;
        }
        __syncthreads();
    }

    float b0v = bias[colBase + c0 + 0];
    float b1v = bias[colBase + c0 + 1];
    float b2v = bias[colBase + c0 + 2];
    float b3v = bias[colBase + c0 + 3];
#pragma unroll
    for (int rp = 0; rp < 2; rp++) {
        float2 d0 = unpack2(ad[rp][0]), x0 = unpack2(ax[rp][0]);
        float2 d1 = unpack2(ad[rp][1]), x1 = unpack2(ax[rp][1]);
        float4 e, o;
        e.x = fmaxf(d0.x + b0v, 0.f);
        e.y = fmaxf(x0.x + b1v, 0.f);
        e.z = fmaxf(d1.x + b2v, 0.f);
        e.w = fmaxf(x1.x + b3v, 0.f);
        o.x = fmaxf(x0.y + b0v, 0.f);
        o.y = fmaxf(d0.y + b1v, 0.f);
        o.z = fmaxf(x1.y + b2v, 0.f);
        o.w = fmaxf(d1.y + b3v, 0.f);
        *(float4*)&C[(rowBase + r0 + 2 * rp) * N + colBase + c0] = e;
        *(float4*)&C[(rowBase + r0 + 2 * rp + 1) * N + colBase + c0] = o;
    }
}

// ---------------- solver helper: MAC a 4-k batch -----------------------------
__device__ __forceinline__ void mac4(u64 ad[4][2], u64 ax[4][2],
                                     const u64x2 wb[4],
                                     const float (*zsrc)[8], int k0) {
#pragma unroll
    for (int j = 0; j < 4; j++) {
        u64x2 za = *(const u64x2*)&zsrc[k0 + j][0];
        u64x2 zb = *(const u64x2*)&zsrc[k0 + j][4];
        u64 zp[4] = {za.x, za.y, zb.x, zb.y};
        u64 wp[2] = {wb[j].x, wb[j].y};
#pragma unroll
        for (int cp = 0; cp < 2; cp++) {
            u64 ws = swp(wp[cp]);
#pragma unroll
            for (int rp = 0; rp < 4; rp++) {
                FFMA2(ad[rp][cp], zp[rp], wp[cp]);
                FFMA2(ax[rp][cp], zp[rp], ws);
            }
        }
    }
}

// MAC 32 k's with register-double-buffered weight batches (4 k per batch).
__device__ __forceinline__ void mac32_pipelined(u64 ad[4][2], u64 ax[4][2],
                                                const float* __restrict__ wptr,
                                                const float (*zsrc)[8],
                                                int kbase) {
    u64x2 wb0[4], wb1[4];
#pragma unroll
    for (int j = 0; j < 4; j++) wb0[j] = *(const u64x2*)(wptr + j * 256);
#pragma unroll
    for (int b = 0; b < 8; b++) {
        if (b + 1 < 8) {
            if (b & 1) {
#pragma unroll
                for (int j = 0; j < 4; j++)
                    wb0[j] = *(const u64x2*)(wptr + ((b + 1) * 4 + j) * 256);
            } else {
#pragma unroll
                for (int j = 0; j < 4; j++)
                    wb1[j] = *(const u64x2*)(wptr + ((b + 1) * 4 + j) * 256);
            }
        }
        mac4(ad, ax, (b & 1) ? wb1 : wb0, zsrc, kbase + b * 4);
    }
}

// ---------------- persistent solver: 512 threads, pipelined weights ----------
// (unchanged from R9: 156us, fma=38%)
__global__ __launch_bounds__(512) void solver_kernel(const float* __restrict__ b2,
                                                     const float* __restrict__ bvec,
                                                     float* __restrict__ outp) {
    extern __shared__ __align__(16) char sm[];
    float(*zcol)[8] = (float(*)[8])sm;            // [256][8]   8192 @0
    u64(*psum)[17] = (u64(*)[17])(sm + 8192);     // [512][17] 69632 @8192
    float(*hcol)[8] = (float(*)[8])(sm + 8192);   // alias over psum
    float* Asm = (float*)(sm + 77824);            // 131072 @77824
    float* bvs = (float*)(sm + 208896);           // 512
    u64* bps = (u64*)(sm + 209408);               // 1024

    const int t = threadIdx.x;
    const int r0 = blockIdx.x * 8;
    float* const zoutp = outp;
    float* const out0p = outp + 1024 * 256;

    const int kg = t >> 6;   // 0..7
    const int cg = t & 63;   // 0..63
    const int c0 = cg * 4;
    const int kgr = t >> 5;  // 0..15
    const int ag = t & 31;   // 0..31
    const int ca0 = ag * 4;

    if (t < 128) {
        bvs[t] = bvec[t];
        bps[t] = *(const u64*)&g_biasproj[2 * t];
    }
    {
        const float4* src = (const float4*)g_AT;
        float4* dst = (float4*)Asm;
#pragma unroll
        for (int i = t; i < 8192; i += 512) dst[i] = src[i];
    }

    u64 ad[4][2], ax[4][2];

    // ---- phase A: out = h2 rows @ W2T + b2 (K=1024, 4 chunks) ----
#pragma unroll
    for (int rp = 0; rp < 4; rp++)
#pragma unroll
        for (int cp = 0; cp < 2; cp++) ad[rp][cp] = ax[rp][cp] = 0ull;

    for (int kc = 0; kc < 1024; kc += 256) {
        __syncthreads();
#pragma unroll
        for (int jj = 0; jj < 4; jj++) {
            int idx = t + 512 * jj;
            int k = idx & 255, r = idx >> 8;
            hcol[k][r] = g_h2[(r0 + r) * 1024 + kc + k];
        }
        __syncthreads();
        mac32_pipelined(ad, ax, g_W2T + (kc + kg * 32) * 256 + c0, hcol,
                        kg * 32);
    }
    __syncthreads();
#pragma unroll
    for (int rp = 0; rp < 4; rp++)
#pragma unroll
        for (int cp = 0; cp < 2; cp++) {
            psum[t][rp * 4 + cp * 2 + 0] = ad[rp][cp];
            psum[t][rp * 4 + cp * 2 + 1] = ax[rp][cp];
        }
    __syncthreads();
#pragma unroll
    for (int uu = 0; uu < 2; uu++) {
        int u = t * 2 + uu;
        int cg2 = u >> 4, j = u & 15;
        int rp = j >> 2, cp = (j >> 1) & 1, dx = j & 1;
        u64 s = psum[cg2][j];
#pragma unroll
        for (int q = 1; q < 8; q++) ADD2(s, psum[q * 64 + cg2][j]);
        int c = 4 * cg2 + 2 * cp;
        u64 bb = *(const u64*)&b2[c];
        if (dx) bb = swp(bb);
        ADD2(s, bb);
        float2 v = unpack2(s);
        int cL = c + dx, cH = c + 1 - dx;
        int re = 2 * rp, ro = 2 * rp + 1;
        zcol[cL][re] = v.x;
        zcol[cH][ro] = v.y;
        out0p[(r0 + re) * 256 + cL] = v.x;
        out0p[(r0 + ro) * 256 + cH] = v.y;
    }
    __syncthreads();

    // ---- 20 fixed iterations, 4 syncthreads each ----
    for (int it = 0; it < 20; it++) {
#pragma unroll
        for (int rp = 0; rp < 4; rp++)
#pragma unroll
            for (int cp = 0; cp < 2; cp++) ad[rp][cp] = ax[rp][cp] = 0ull;
        mac32_pipelined(ad, ax, g_WzT + (kg * 32) * 256 + c0, zcol, kg * 32);
#pragma unroll
        for (int rp = 0; rp < 4; rp++)
#pragma unroll
            for (int cp = 0; cp < 2; cp++) {
                psum[t][rp * 4 + cp * 2 + 0] = ad[rp][cp];
                psum[t][rp * 4 + cp * 2 + 1] = ax[rp][cp];
            }
        __syncthreads();  // (1) psum ready
#pragma unroll
        for (int uu = 0; uu < 2; uu++) {
            int u = t * 2 + uu;
            int cg2 = u >> 4, j = u & 15;
            int rp = j >> 2, cp = (j >> 1) & 1, dx = j & 1;
            u64 s = psum[cg2][j];
#pragma unroll
            for (int q = 1; q < 8; q++) ADD2(s, psum[q * 64 + cg2][j]);
            int c = 4 * cg2 + 2 * cp;
            u64 bb = bps[2 * cg2 + cp];
            if (dx) bb = swp(bb);
            ADD2(s, bb);
            float2 v = unpack2(s);
            if (cg2 >= 16) {
                v.x = fmaxf(v.x, 0.f);
                v.y = fmaxf(v.y, 0.f);
            }
            zcol[c + dx][2 * rp] = v.x;
            zcol[c + 1 - dx][2 * rp + 1] = v.y;
        }
        __syncthreads();  // (2) zcol ready, psum reads done

        u64 rd[4][2], rx[4][2];
#pragma unroll
        for (int rp = 0; rp < 4; rp++)
#pragma unroll
            for (int cp = 0; cp < 2; cp++) rd[rp][cp] = rx[rp][cp] = 0ull;
#pragma unroll 4
        for (int kk = 0; kk < 16; kk++) {
            int k = kgr * 16 + kk;
            u64x2 za = *(const u64x2*)&zcol[k][0];
            u64x2 zb = *(const u64x2*)&zcol[k][4];
            u64x2 av = *(const u64x2*)&Asm[k * 128 + ca0];
            u64 zp[4] = {za.x, za.y, zb.x, zb.y};
            u64 ap[2] = {av.x, av.y};
#pragma unroll
            for (int cp = 0; cp < 2; cp++) {
                u64 as = swp(ap[cp]);
#pragma unroll
                for (int rp = 0; rp < 4; rp++) {
                    FFMA2(rd[rp][cp], zp[rp], ap[cp]);
                    FFMA2(rx[rp][cp], zp[rp], as);
                }
            }
        }
#pragma unroll
        for (int rp = 0; rp < 4; rp++)
#pragma unroll
            for (int cp = 0; cp < 2; cp++) {
                psum[t][rp * 4 + cp * 2 + 0] = rd[rp][cp];
                psum[t][rp * 4 + cp * 2 + 1] = rx[rp][cp];
            }
        __syncthreads();  // (3) psum ready
        float m;
        {
            int u = t;
            int ag2 = u >> 4, j = u & 15;
            int cp = (j >> 1) & 1, dx = j & 1;
            u64 s = psum[ag2][j];
#pragma unroll
            for (int q = 1; q < 16; q++) ADD2(s, psum[q * 32 + ag2][j]);
            float2 v = unpack2(s);
            int c = 4 * ag2 + 2 * cp;
            m = fmaxf(fabsf(v.x - bvs[c + dx]), fabsf(v.y - bvs[c + 1 - dx]));
        }
#pragma unroll
        for (int o = 16; o; o >>= 1) m = fmaxf(m, __shfl_xor_sync(~0u, m, o));
        if ((t & 31) == 0) atomicMax(&g_res_arr[it], __float_as_uint(m));
        __syncthreads();  // (4) psum reads done before next z-MAC writes
    }

    // write z_star directly to d_out
#pragma unroll
    for (int jj = 0; jj < 4; jj++) {
        int idx = t + 512 * jj;
        int c = idx & 255, r = idx >> 8;
        zoutp[(r0 + r) * 256 + c] = zcol[c][r];
    }
    __syncthreads();
    __threadfence();
    if (t == 0) {
        if (atomicAdd(&g_solver_done, 1u) == NBLK - 1) {
            int it = 21;
            for (int tt = 0; tt < 20; tt++) {
                unsigned rb = atomicAdd(&g_res_arr[tt], 0u);
                if (__uint_as_float(rb) <= F_TOL_F) {
                    it = tt + 2;
                    break;
                }
            }
            outp[2 * 1024 * 256] = (float)it;
        }
    }
}

// ---------------- launch ------------------------------------------------------
extern "C" void kernel_launch(void* const* d_in, const int* in_sizes, int n_in,
                              void* d_out, int out_size) {
    const float* b_primal = (const float*)d_in[0];
    const float* W0 = (const float*)d_in[1];
    const float* b0 = (const float*)d_in[2];
    const float* W1 = (const float*)d_in[3];
    const float* b1 = (const float*)d_in[4];
    const float* W2 = (const float*)d_in[5];
    const float* b2 = (const float*)d_in[6];
    const float* Amat = (const float*)d_in[7];
    const float* b_vec = (const float*)d_in[8];
    const float* WzProj = (const float*)d_in[9];
    const float* WbProj = (const float*)d_in[10];

    float *h1, *h2;
    cudaGetSymbolAddress((void**)&h1, g_h1);
    cudaGetSymbolAddress((void**)&h2, g_h2);

    static int smem_set = 0;
    if (!smem_set) {
        cudaFuncSetAttribute(solver_kernel,
                             cudaFuncAttributeMaxDynamicSharedMemorySize,
                             SOLVER_SMEM);
        smem_set = 1;
    }

    prep_kernel<<<353, 1024>>>(W2, WzProj, Amat, b_vec, WbProj);

    // h1 = relu(b_primal @ W0^T + b0)   M=1024 N=1024 K=512
    gemm_relu_f2<<<dim3(16, 8), 512>>>(b_primal, W0, b0, h1, 1024, 1024, 512);
    // h2 = relu(h1 @ W1^T + b1)         M=1024 N=1024 K=1024
    gemm_relu_f2<<<dim3(16, 8), 512>>>(h1, W1, b1, h2, 1024, 1024, 1024);

    // fused: out + 20-iteration fixed-point loop, writes d_out directly
    solver_kernel<<<NBLK, 512, SOLVER_SMEM>>>(b2, b_vec, (float*)d_out);
}

// round 11
// speedup vs baseline: 1.1121x; 1.1121x over previous
#include <cuda_runtime.h>
#include <math.h>

typedef unsigned long long u64;
typedef ulonglong2 u64x2;

#define F_TOL_F 1e-6f
#define NBLK 128
#define SOLVER_SMEM 210496

// ---------------- device-global scratch (no allocations allowed) ------------
__device__ float g_h1[1024 * 1024];
__device__ float g_h2[1024 * 1024];
__device__ float g_W2T[1024 * 256];
__device__ float g_WzT[256 * 256];
__device__ float g_AT[256 * 128];
__device__ float g_biasproj[256];
__device__ unsigned g_res_arr[20];
__device__ unsigned g_solver_done;

// ---------------- packed fp32x2 (Blackwell double-rate fp32) ----------------
#define FFMA2(acc, a, b) \
    asm("fma.rn.f32x2 %0, %1, %2, %0;" : "+l"(acc) : "l"(a), "l"(b))
#define ADD2(acc, a) \
    asm("add.rn.f32x2 %0, %1, %0;" : "+l"(acc) : "l"(a))

__device__ __forceinline__ float2 unpack2(u64 v) {
    float2 p;
    asm("mov.b64 {%0,%1}, %2;" : "=f"(p.x), "=f"(p.y) : "l"(v));
    return p;
}
__device__ __forceinline__ u64 pack2(float lo, float hi) {
    u64 r;
    asm("mov.b64 %0, {%1,%2};" : "=l"(r) : "f"(lo), "f"(hi));
    return r;
}
__device__ __forceinline__ u64 swp(u64 v) {
    float2 f = unpack2(v);
    return pack2(f.y, f.x);
}

// ---------------- fused prep: 3 transposes + biasproj + state reset ---------
__global__ void prep_kernel(const float* __restrict__ W2,
                            const float* __restrict__ Wz,
                            const float* __restrict__ Am,
                            const float* __restrict__ bvec,
                            const float* __restrict__ WbP) {
    __shared__ float tb[32][33];
    const int b = blockIdx.x;
    const int t = threadIdx.x;
    const int tx = t & 31, ty = t >> 5;

    const float* in;
    float* out;
    int R, C, bx, by;
    if (b < 256) {
        in = W2; out = g_W2T; R = 256; C = 1024; bx = b & 31; by = b >> 5;
    } else if (b < 320) {
        int bb = b - 256;
        in = Wz; out = g_WzT; R = 256; C = 256; bx = bb & 7; by = bb >> 3;
    } else if (b < 352) {
        int bb = b - 320;
        in = Am; out = g_AT; R = 128; C = 256; bx = bb & 7; by = bb >> 3;
    } else {
        if (t < 20) g_res_arr[t] = 0u;
        if (t == 32) g_solver_done = 0u;
        if (t >= 256 && t < 512) {
            int j = t - 256;
            float s = 0.f;
#pragma unroll 8
            for (int i = 0; i < 128; i++) s += bvec[i] * WbP[j * 128 + i];
            g_biasproj[j] = s;
        }
        return;
    }
    int c = bx * 32 + tx, r = by * 32 + ty;
    tb[ty][tx] = in[r * C + c];
    __syncthreads();
    int oc = by * 32 + tx;
    int orr = bx * 32 + ty;
    out[orr * R + oc] = tb[tx][ty];
}

// ---------------- FFMA2 SGEMM: C = relu(A @ B^T + bias) ----------------------
// R7 config (best measured): BM=128, BN=64, BK=16 double-buffered, 256 threads,
// 8m x 4n per thread, row-pair packed accumulators + w-swap trick.
__global__ __launch_bounds__(256, 2) void gemm_relu_f2(
    const float* __restrict__ A, const float* __restrict__ B,
    const float* __restrict__ bias, float* __restrict__ C,
    int M, int N, int K) {
    __shared__ __align__(16) float As[2][16][128];
    __shared__ __align__(16) float Bs[2][16][64];

    const int t = threadIdx.x;
    const int tx = t & 15, ty = t >> 4;
    const int rowBase = blockIdx.y * 128;
    const int colBase = blockIdx.x * 64;
    const int c0 = 4 * tx, r0 = 8 * ty;

    const int rA = t >> 2, kseg = (t & 3) * 4;

    const float* Aload = A + (rowBase + rA) * K + kseg;
    const float* Aload2 = A + (rowBase + rA + 64) * K + kseg;
    const float* Bload = B + (colBase + rA) * K + kseg;

    u64 ad[4][2], ax[4][2];
#pragma unroll
    for (int rp = 0; rp < 4; rp++)
#pragma unroll
        for (int cp = 0; cp < 2; cp++) ad[rp][cp] = ax[rp][cp] = 0ull;

    {
        float4 a1 = *(const float4*)(Aload);
        float4 a2 = *(const float4*)(Aload2);
        float4 bv = *(const float4*)(Bload);
#pragma unroll
        for (int j = 0; j < 4; j++) {
            As[0][kseg + j][rA] = ((const float*)&a1)[j];
            As[0][kseg + j][rA + 64] = ((const float*)&a2)[j];
            Bs[0][kseg + j][rA] = ((const float*)&bv)[j];
        }
    }
    __syncthreads();

    const int nt = K >> 4;
    for (int tt = 0; tt < nt; tt++) {
        const int buf = tt & 1;
        float4 a1, a2, bv;
        if (tt + 1 < nt) {
            a1 = *(const float4*)(Aload + (tt + 1) * 16);
            a2 = *(const float4*)(Aload2 + (tt + 1) * 16);
            bv = *(const float4*)(Bload + (tt + 1) * 16);
        }
#pragma unroll
        for (int k = 0; k < 16; k++) {
            u64x2 za = *(const u64x2*)&As[buf][k][r0];
            u64x2 zb = *(const u64x2*)&As[buf][k][r0 + 4];
            u64x2 wv = *(const u64x2*)&Bs[buf][k][c0];
            u64 zp[4] = {za.x, za.y, zb.x, zb.y};
            u64 wp[2] = {wv.x, wv.y};
#pragma unroll
            for (int cp = 0; cp < 2; cp++) {
                u64 ws = swp(wp[cp]);
#pragma unroll
                for (int rp = 0; rp < 4; rp++) {
                    FFMA2(ad[rp][cp], zp[rp], wp[cp]);
                    FFMA2(ax[rp][cp], zp[rp], ws);
                }
            }
        }
        if (tt + 1 < nt) {
            const int nb = buf ^ 1;
#pragma unroll
            for (int j = 0; j < 4; j++) {
                As[nb][kseg + j][rA] = ((const float*)&a1)[j];
                As[nb][kseg + j][rA + 64] = ((const float*)&a2)[j];
                Bs[nb][kseg + j][rA] = ((const float*)&bv)[j];
            }
        }
        __syncthreads();
    }

    float b0v = bias[colBase + c0 + 0];
    float b1v = bias[colBase + c0 + 1];
    float b2v = bias[colBase + c0 + 2];
    float b3v = bias[colBase + c0 + 3];
#pragma unroll
    for (int rp = 0; rp < 4; rp++) {
        float2 d0 = unpack2(ad[rp][0]), x0 = unpack2(ax[rp][0]);
        float2 d1 = unpack2(ad[rp][1]), x1 = unpack2(ax[rp][1]);
        float4 e, o;
        e.x = fmaxf(d0.x + b0v, 0.f);
        e.y = fmaxf(x0.x + b1v, 0.f);
        e.z = fmaxf(d1.x + b2v, 0.f);
        e.w = fmaxf(x1.x + b3v, 0.f);
        o.x = fmaxf(x0.y + b0v, 0.f);
        o.y = fmaxf(d0.y + b1v, 0.f);
        o.z = fmaxf(x1.y + b2v, 0.f);
        o.w = fmaxf(d1.y + b3v, 0.f);
        *(float4*)&C[(rowBase + r0 + 2 * rp) * N + colBase + c0] = e;
        *(float4*)&C[(rowBase + r0 + 2 * rp + 1) * N + colBase + c0] = o;
    }
}

// ---------------- solver helper: MAC a 4-k batch -----------------------------
__device__ __forceinline__ void mac4(u64 ad[4][2], u64 ax[4][2],
                                     const u64x2 wb[4],
                                     const float (*zsrc)[8], int k0) {
#pragma unroll
    for (int j = 0; j < 4; j++) {
        u64x2 za = *(const u64x2*)&zsrc[k0 + j][0];
        u64x2 zb = *(const u64x2*)&zsrc[k0 + j][4];
        u64 zp[4] = {za.x, za.y, zb.x, zb.y};
        u64 wp[2] = {wb[j].x, wb[j].y};
#pragma unroll
        for (int cp = 0; cp < 2; cp++) {
            u64 ws = swp(wp[cp]);
#pragma unroll
            for (int rp = 0; rp < 4; rp++) {
                FFMA2(ad[rp][cp], zp[rp], wp[cp]);
                FFMA2(ax[rp][cp], zp[rp], ws);
            }
        }
    }
}

// MAC 32 k's with register-double-buffered weight batches (4 k per batch).
__device__ __forceinline__ void mac32_pipelined(u64 ad[4][2], u64 ax[4][2],
                                                const float* __restrict__ wptr,
                                                const float (*zsrc)[8],
                                                int kbase) {
    u64x2 wb0[4], wb1[4];
#pragma unroll
    for (int j = 0; j < 4; j++) wb0[j] = *(const u64x2*)(wptr + j * 256);
#pragma unroll
    for (int b = 0; b < 8; b++) {
        if (b + 1 < 8) {
            if (b & 1) {
#pragma unroll
                for (int j = 0; j < 4; j++)
                    wb0[j] = *(const u64x2*)(wptr + ((b + 1) * 4 + j) * 256);
            } else {
#pragma unroll
                for (int j = 0; j < 4; j++)
                    wb1[j] = *(const u64x2*)(wptr + ((b + 1) * 4 + j) * 256);
            }
        }
        mac4(ad, ax, (b & 1) ? wb1 : wb0, zsrc, kbase + b * 4);
    }
}

// ---------------- persistent solver: 512 threads, pipelined weights ----------
// (unchanged from R10: 156us, fma=38%)
__global__ __launch_bounds__(512) void solver_kernel(const float* __restrict__ b2,
                                                     const float* __restrict__ bvec,
                                                     float* __restrict__ outp) {
    extern __shared__ __align__(16) char sm[];
    float(*zcol)[8] = (float(*)[8])sm;            // [256][8]   8192 @0
    u64(*psum)[17] = (u64(*)[17])(sm + 8192);     // [512][17] 69632 @8192
    float(*hcol)[8] = (float(*)[8])(sm + 8192);   // alias over psum
    float* Asm = (float*)(sm + 77824);            // 131072 @77824
    float* bvs = (float*)(sm + 208896);           // 512
    u64* bps = (u64*)(sm + 209408);               // 1024

    const int t = threadIdx.x;
    const int r0 = blockIdx.x * 8;
    float* const zoutp = outp;
    float* const out0p = outp + 1024 * 256;

    const int kg = t >> 6;   // 0..7
    const int cg = t & 63;   // 0..63
    const int c0 = cg * 4;
    const int kgr = t >> 5;  // 0..15
    const int ag = t & 31;   // 0..31
    const int ca0 = ag * 4;

    if (t < 128) {
        bvs[t] = bvec[t];
        bps[t] = *(const u64*)&g_biasproj[2 * t];
    }
    {
        const float4* src = (const float4*)g_AT;
        float4* dst = (float4*)Asm;
#pragma unroll
        for (int i = t; i < 8192; i += 512) dst[i] = src[i];
    }

    u64 ad[4][2], ax[4][2];

    // ---- phase A: out = h2 rows @ W2T + b2 (K=1024, 4 chunks) ----
#pragma unroll
    for (int rp = 0; rp < 4; rp++)
#pragma unroll
        for (int cp = 0; cp < 2; cp++) ad[rp][cp] = ax[rp][cp] = 0ull;

    for (int kc = 0; kc < 1024; kc += 256) {
        __syncthreads();
#pragma unroll
        for (int jj = 0; jj < 4; jj++) {
            int idx = t + 512 * jj;
            int k = idx & 255, r = idx >> 8;
            hcol[k][r] = g_h2[(r0 + r) * 1024 + kc + k];
        }
        __syncthreads();
        mac32_pipelined(ad, ax, g_W2T + (kc + kg * 32) * 256 + c0, hcol,
                        kg * 32);
    }
    __syncthreads();
#pragma unroll
    for (int rp = 0; rp < 4; rp++)
#pragma unroll
        for (int cp = 0; cp < 2; cp++) {
            psum[t][rp * 4 + cp * 2 + 0] = ad[rp][cp];
            psum[t][rp * 4 + cp * 2 + 1] = ax[rp][cp];
        }
    __syncthreads();
#pragma unroll
    for (int uu = 0; uu < 2; uu++) {
        int u = t * 2 + uu;
        int cg2 = u >> 4, j = u & 15;
        int rp = j >> 2, cp = (j >> 1) & 1, dx = j & 1;
        u64 s = psum[cg2][j];
#pragma unroll
        for (int q = 1; q < 8; q++) ADD2(s, psum[q * 64 + cg2][j]);
        int c = 4 * cg2 + 2 * cp;
        u64 bb = *(const u64*)&b2[c];
        if (dx) bb = swp(bb);
        ADD2(s, bb);
        float2 v = unpack2(s);
        int cL = c + dx, cH = c + 1 - dx;
        int re = 2 * rp, ro = 2 * rp + 1;
        zcol[cL][re] = v.x;
        zcol[cH][ro] = v.y;
        out0p[(r0 + re) * 256 + cL] = v.x;
        out0p[(r0 + ro) * 256 + cH] = v.y;
    }
    __syncthreads();

    // ---- 20 fixed iterations, 4 syncthreads each ----
    for (int it = 0; it < 20; it++) {
#pragma unroll
        for (int rp = 0; rp < 4; rp++)
#pragma unroll
            for (int cp = 0; cp < 2; cp++) ad[rp][cp] = ax[rp][cp] = 0ull;
        mac32_pipelined(ad, ax, g_WzT + (kg * 32) * 256 + c0, zcol, kg * 32);
#pragma unroll
        for (int rp = 0; rp < 4; rp++)
#pragma unroll
            for (int cp = 0; cp < 2; cp++) {
                psum[t][rp * 4 + cp * 2 + 0] = ad[rp][cp];
                psum[t][rp * 4 + cp * 2 + 1] = ax[rp][cp];
            }
        __syncthreads();  // (1) psum ready
#pragma unroll
        for (int uu = 0; uu < 2; uu++) {
            int u = t * 2 + uu;
            int cg2 = u >> 4, j = u & 15;
            int rp = j >> 2, cp = (j >> 1) & 1, dx = j & 1;
            u64 s = psum[cg2][j];
#pragma unroll
            for (int q = 1; q < 8; q++) ADD2(s, psum[q * 64 + cg2][j]);
            int c = 4 * cg2 + 2 * cp;
            u64 bb = bps[2 * cg2 + cp];
            if (dx) bb = swp(bb);
            ADD2(s, bb);
            float2 v = unpack2(s);
            if (cg2 >= 16) {
                v.x = fmaxf(v.x, 0.f);
                v.y = fmaxf(v.y, 0.f);
            }
            zcol[c + dx][2 * rp] = v.x;
            zcol[c + 1 - dx][2 * rp + 1] = v.y;
        }
        __syncthreads();  // (2) zcol ready, psum reads done

        u64 rd[4][2], rx[4][2];
#pragma unroll
        for (int rp = 0; rp < 4; rp++)
#pragma unroll
            for (int cp = 0; cp < 2; cp++) rd[rp][cp] = rx[rp][cp] = 0ull;
#pragma unroll 4
        for (int kk = 0; kk < 16; kk++) {
            int k = kgr * 16 + kk;
            u64x2 za = *(const u64x2*)&zcol[k][0];
            u64x2 zb = *(const u64x2*)&zcol[k][4];
            u64x2 av = *(const u64x2*)&Asm[k * 128 + ca0];
            u64 zp[4] = {za.x, za.y, zb.x, zb.y};
            u64 ap[2] = {av.x, av.y};
#pragma unroll
            for (int cp = 0; cp < 2; cp++) {
                u64 as = swp(ap[cp]);
#pragma unroll
                for (int rp = 0; rp < 4; rp++) {
                    FFMA2(rd[rp][cp], zp[rp], ap[cp]);
                    FFMA2(rx[rp][cp], zp[rp], as);
                }
            }
        }
#pragma unroll
        for (int rp = 0; rp < 4; rp++)
#pragma unroll
            for (int cp = 0; cp < 2; cp++) {
                psum[t][rp * 4 + cp * 2 + 0] = rd[rp][cp];
                psum[t][rp * 4 + cp * 2 + 1] = rx[rp][cp];
            }
        __syncthreads();  // (3) psum ready
        float m;
        {
            int u = t;
            int ag2 = u >> 4, j = u & 15;
            int cp = (j >> 1) & 1, dx = j & 1;
            u64 s = psum[ag2][j];
#pragma unroll
            for (int q = 1; q < 16; q++) ADD2(s, psum[q * 32 + ag2][j]);
            float2 v = unpack2(s);
            int c = 4 * ag2 + 2 * cp;
            m = fmaxf(fabsf(v.x - bvs[c + dx]), fabsf(v.y - bvs[c + 1 - dx]));
        }
#pragma unroll
        for (int o = 16; o; o >>= 1) m = fmaxf(m, __shfl_xor_sync(~0u, m, o));
        if ((t & 31) == 0) atomicMax(&g_res_arr[it], __float_as_uint(m));
        __syncthreads();  // (4) psum reads done before next z-MAC writes
    }

    // write z_star directly to d_out
#pragma unroll
    for (int jj = 0; jj < 4; jj++) {
        int idx = t + 512 * jj;
        int c = idx & 255, r = idx >> 8;
        zoutp[(r0 + r) * 256 + c] = zcol[c][r];
    }
    __syncthreads();
    __threadfence();
    if (t == 0) {
        if (atomicAdd(&g_solver_done, 1u) == NBLK - 1) {
            int it = 21;
            for (int tt = 0; tt < 20; tt++) {
                unsigned rb = atomicAdd(&g_res_arr[tt], 0u);
                if (__uint_as_float(rb) <= F_TOL_F) {
                    it = tt + 2;
                    break;
                }
            }
            outp[2 * 1024 * 256] = (float)it;
        }
    }
}

// ---------------- launch ------------------------------------------------------
extern "C" void kernel_launch(void* const* d_in, const int* in_sizes, int n_in,
                              void* d_out, int out_size) {
    const float* b_primal = (const float*)d_in[0];
    const float* W0 = (const float*)d_in[1];
    const float* b0 = (const float*)d_in[2];
    const float* W1 = (const float*)d_in[3];
    const float* b1 = (const float*)d_in[4];
    const float* W2 = (const float*)d_in[5];
    const float* b2 = (const float*)d_in[6];
    const float* Amat = (const float*)d_in[7];
    const float* b_vec = (const float*)d_in[8];
    const float* WzProj = (const float*)d_in[9];
    const float* WbProj = (const float*)d_in[10];

    float *h1, *h2;
    cudaGetSymbolAddress((void**)&h1, g_h1);
    cudaGetSymbolAddress((void**)&h2, g_h2);

    static int smem_set = 0;
    if (!smem_set) {
        cudaFuncSetAttribute(solver_kernel,
                             cudaFuncAttributeMaxDynamicSharedMemorySize,
                             SOLVER_SMEM);
        smem_set = 1;
    }

    prep_kernel<<<353, 1024>>>(W2, WzProj, Amat, b_vec, WbProj);

    // h1 = relu(b_primal @ W0^T + b0)   M=1024 N=1024 K=512
    gemm_relu_f2<<<dim3(16, 8), 256>>>(b_primal, W0, b0, h1, 1024, 1024, 512);
    // h2 = relu(h1 @ W1^T + b1)         M=1024 N=1024 K=1024
    gemm_relu_f2<<<dim3(16, 8), 256>>>(h1, W1, b1, h2, 1024, 1024, 1024);

    // fused: out + 20-iteration fixed-point loop, writes d_out directly
    solver_kernel<<<NBLK, 512, SOLVER_SMEM>>>(b2, b_vec, (float*)d_out);
}

// round 12
// speedup vs baseline: 1.1489x; 1.0331x over previous
#include <cuda_runtime.h>
#include <math.h>

typedef unsigned long long u64;
typedef ulonglong2 u64x2;

#define F_TOL_F 1e-6f
#define NBLK 128
#define SOLVER_SMEM 62976

// ---------------- device-global scratch (no allocations allowed) ------------
__device__ float g_h1[1024 * 1024];
__device__ float g_h2[1024 * 1024];
__device__ float g_W2T[1024 * 256];
__device__ float g_WzT[256 * 256];
__device__ float g_AT[256 * 128];
__device__ float g_biasproj[256];
__device__ unsigned g_res_arr[20];
__device__ unsigned g_solver_done;

// ---------------- packed fp32x2 (Blackwell double-rate fp32) ----------------
#define FFMA2(acc, a, b) \
    asm("fma.rn.f32x2 %0, %1, %2, %0;" : "+l"(acc) : "l"(a), "l"(b))
#define ADD2(acc, a) \
    asm("add.rn.f32x2 %0, %1, %0;" : "+l"(acc) : "l"(a))

__device__ __forceinline__ float2 unpack2(u64 v) {
    float2 p;
    asm("mov.b64 {%0,%1}, %2;" : "=f"(p.x), "=f"(p.y) : "l"(v));
    return p;
}
__device__ __forceinline__ u64 pack2(float lo, float hi) {
    u64 r;
    asm("mov.b64 %0, {%1,%2};" : "=l"(r) : "f"(lo), "f"(hi));
    return r;
}
__device__ __forceinline__ u64 swp(u64 v) {
    float2 f = unpack2(v);
    return pack2(f.y, f.x);
}

// ---------------- fused prep: 3 transposes + biasproj + state reset ---------
__global__ void prep_kernel(const float* __restrict__ W2,
                            const float* __restrict__ Wz,
                            const float* __restrict__ Am,
                            const float* __restrict__ bvec,
                            const float* __restrict__ WbP) {
    __shared__ float tb[32][33];
    const int b = blockIdx.x;
    const int t = threadIdx.x;
    const int tx = t & 31, ty = t >> 5;

    const float* in;
    float* out;
    int R, C, bx, by;
    if (b < 256) {
        in = W2; out = g_W2T; R = 256; C = 1024; bx = b & 31; by = b >> 5;
    } else if (b < 320) {
        int bb = b - 256;
        in = Wz; out = g_WzT; R = 256; C = 256; bx = bb & 7; by = bb >> 3;
    } else if (b < 352) {
        int bb = b - 320;
        in = Am; out = g_AT; R = 128; C = 256; bx = bb & 7; by = bb >> 3;
    } else {
        if (t < 20) g_res_arr[t] = 0u;
        if (t == 32) g_solver_done = 0u;
        if (t >= 256 && t < 512) {
            int j = t - 256;
            float s = 0.f;
#pragma unroll 8
            for (int i = 0; i < 128; i++) s += bvec[i] * WbP[j * 128 + i];
            g_biasproj[j] = s;
        }
        return;
    }
    int c = bx * 32 + tx, r = by * 32 + ty;
    tb[ty][tx] = in[r * C + c];
    __syncthreads();
    int oc = by * 32 + tx;
    int orr = bx * 32 + ty;
    out[orr * R + oc] = tb[tx][ty];
}

// ---------------- FFMA2 SGEMM: C = relu(A @ B^T + bias) ----------------------
// R7 config (best measured): BM=128, BN=64, BK=16 double-buffered, 256 threads,
// 8m x 4n per thread, row-pair packed accumulators + w-swap trick.
__global__ __launch_bounds__(256, 2) void gemm_relu_f2(
    const float* __restrict__ A, const float* __restrict__ B,
    const float* __restrict__ bias, float* __restrict__ C,
    int M, int N, int K) {
    __shared__ __align__(16) float As[2][16][128];
    __shared__ __align__(16) float Bs[2][16][64];

    const int t = threadIdx.x;
    const int tx = t & 15, ty = t >> 4;
    const int rowBase = blockIdx.y * 128;
    const int colBase = blockIdx.x * 64;
    const int c0 = 4 * tx, r0 = 8 * ty;

    const int rA = t >> 2, kseg = (t & 3) * 4;

    const float* Aload = A + (rowBase + rA) * K + kseg;
    const float* Aload2 = A + (rowBase + rA + 64) * K + kseg;
    const float* Bload = B + (colBase + rA) * K + kseg;

    u64 ad[4][2], ax[4][2];
#pragma unroll
    for (int rp = 0; rp < 4; rp++)
#pragma unroll
        for (int cp = 0; cp < 2; cp++) ad[rp][cp] = ax[rp][cp] = 0ull;

    {
        float4 a1 = *(const float4*)(Aload);
        float4 a2 = *(const float4*)(Aload2);
        float4 bv = *(const float4*)(Bload);
#pragma unroll
        for (int j = 0; j < 4; j++) {
            As[0][kseg + j][rA] = ((const float*)&a1)[j];
            As[0][kseg + j][rA + 64] = ((const float*)&a2)[j];
            Bs[0][kseg + j][rA] = ((const float*)&bv)[j];
        }
    }
    __syncthreads();

    const int nt = K >> 4;
    for (int tt = 0; tt < nt; tt++) {
        const int buf = tt & 1;
        float4 a1, a2, bv;
        if (tt + 1 < nt) {
            a1 = *(const float4*)(Aload + (tt + 1) * 16);
            a2 = *(const float4*)(Aload2 + (tt + 1) * 16);
            bv = *(const float4*)(Bload + (tt + 1) * 16);
        }
#pragma unroll
        for (int k = 0; k < 16; k++) {
            u64x2 za = *(const u64x2*)&As[buf][k][r0];
            u64x2 zb = *(const u64x2*)&As[buf][k][r0 + 4];
            u64x2 wv = *(const u64x2*)&Bs[buf][k][c0];
            u64 zp[4] = {za.x, za.y, zb.x, zb.y};
            u64 wp[2] = {wv.x, wv.y};
#pragma unroll
            for (int cp = 0; cp < 2; cp++) {
                u64 ws = swp(wp[cp]);
#pragma unroll
                for (int rp = 0; rp < 4; rp++) {
                    FFMA2(ad[rp][cp], zp[rp], wp[cp]);
                    FFMA2(ax[rp][cp], zp[rp], ws);
                }
            }
        }
        if (tt + 1 < nt) {
            const int nb = buf ^ 1;
#pragma unroll
            for (int j = 0; j < 4; j++) {
                As[nb][kseg + j][rA] = ((const float*)&a1)[j];
                As[nb][kseg + j][rA + 64] = ((const float*)&a2)[j];
                Bs[nb][kseg + j][rA] = ((const float*)&bv)[j];
            }
        }
        __syncthreads();
    }

    float b0v = bias[colBase + c0 + 0];
    float b1v = bias[colBase + c0 + 1];
    float b2v = bias[colBase + c0 + 2];
    float b3v = bias[colBase + c0 + 3];
#pragma unroll
    for (int rp = 0; rp < 4; rp++) {
        float2 d0 = unpack2(ad[rp][0]), x0 = unpack2(ax[rp][0]);
        float2 d1 = unpack2(ad[rp][1]), x1 = unpack2(ax[rp][1]);
        float4 e, o;
        e.x = fmaxf(d0.x + b0v, 0.f);
        e.y = fmaxf(x0.x + b1v, 0.f);
        e.z = fmaxf(d1.x + b2v, 0.f);
        e.w = fmaxf(x1.x + b3v, 0.f);
        o.x = fmaxf(x0.y + b0v, 0.f);
        o.y = fmaxf(d0.y + b1v, 0.f);
        o.z = fmaxf(x1.y + b2v, 0.f);
        o.w = fmaxf(d1.y + b3v, 0.f);
        *(float4*)&C[(rowBase + r0 + 2 * rp) * N + colBase + c0] = e;
        *(float4*)&C[(rowBase + r0 + 2 * rp + 1) * N + colBase + c0] = o;
    }
}

// ---------------- solver MAC helpers ------------------------------------------
// z-only MAC over 64 k's (phase A): thread owns 2 w-cols (2cgz, 2cgz+1),
// 4 row-pairs. Register-double-buffered 4-k weight batches.
__device__ __forceinline__ void mac64_z(u64 ad[4], u64 ax[4],
                                        const float* __restrict__ wptr,
                                        const float (*zsrc)[8], int kbase) {
    u64 wb0[4], wb1[4];
#pragma unroll
    for (int j = 0; j < 4; j++) wb0[j] = *(const u64*)(wptr + j * 256);
#pragma unroll
    for (int b = 0; b < 16; b++) {
        if (b + 1 < 16) {
            if (b & 1) {
#pragma unroll
                for (int j = 0; j < 4; j++)
                    wb0[j] = *(const u64*)(wptr + ((b + 1) * 4 + j) * 256);
            } else {
#pragma unroll
                for (int j = 0; j < 4; j++)
                    wb1[j] = *(const u64*)(wptr + ((b + 1) * 4 + j) * 256);
            }
        }
        const u64* wb = (b & 1) ? wb1 : wb0;
#pragma unroll
        for (int j = 0; j < 4; j++) {
            int k = kbase + b * 4 + j;
            u64x2 za = *(const u64x2*)&zsrc[k][0];
            u64x2 zb = *(const u64x2*)&zsrc[k][4];
            u64 zp[4] = {za.x, za.y, zb.x, zb.y};
            u64 w = wb[j], ws = swp(w);
#pragma unroll
            for (int rp = 0; rp < 4; rp++) {
                FFMA2(ad[rp], zp[rp], w);
                FFMA2(ax[rp], zp[rp], ws);
            }
        }
    }
}

// merged MAC: z-update (Wz) + residual (A col cgz) sharing z loads.
__device__ __forceinline__ void mac64_merged(u64 ad[4], u64 ax[4], u64 rd[4],
                                             const float* __restrict__ wptr,
                                             const float* __restrict__ aptr,
                                             const float (*zsrc)[8],
                                             int kbase) {
    u64 wb0[4], wb1[4];
    float ab0[4], ab1[4];
#pragma unroll
    for (int j = 0; j < 4; j++) {
        wb0[j] = *(const u64*)(wptr + j * 256);
        ab0[j] = *(aptr + j * 128);
    }
#pragma unroll
    for (int b = 0; b < 16; b++) {
        if (b + 1 < 16) {
            if (b & 1) {
#pragma unroll
                for (int j = 0; j < 4; j++) {
                    wb0[j] = *(const u64*)(wptr + ((b + 1) * 4 + j) * 256);
                    ab0[j] = *(aptr + ((b + 1) * 4 + j) * 128);
                }
            } else {
#pragma unroll
                for (int j = 0; j < 4; j++) {
                    wb1[j] = *(const u64*)(wptr + ((b + 1) * 4 + j) * 256);
                    ab1[j] = *(aptr + ((b + 1) * 4 + j) * 128);
                }
            }
        }
        const u64* wb = (b & 1) ? wb1 : wb0;
        const float* ab = (b & 1) ? ab1 : ab0;
#pragma unroll
        for (int j = 0; j < 4; j++) {
            int k = kbase + b * 4 + j;
            u64x2 za = *(const u64x2*)&zsrc[k][0];
            u64x2 zb = *(const u64x2*)&zsrc[k][4];
            u64 zp[4] = {za.x, za.y, zb.x, zb.y};
            u64 w = wb[j], ws = swp(w);
            u64 ap = pack2(ab[j], ab[j]);
#pragma unroll
            for (int rp = 0; rp < 4; rp++) {
                FFMA2(ad[rp], zp[rp], w);
                FFMA2(ax[rp], zp[rp], ws);
                FFMA2(rd[rp], zp[rp], ap);
            }
        }
    }
}

// ---------------- persistent solver: merged z-update + residual --------------
// 128 blocks x 512 threads; block b owns rows [8b, 8b+8). z natural: zcol[k][r].
// Thread: kg = t>>7 (4 k-groups x 64k), cgz = t&127 (2 Wz cols / 1 A col).
// Each pass p: z_{p+1} = proj(bias + z_p @ Wz); residual of z_p (p>=1) merged in.
__global__ __launch_bounds__(512) void solver_kernel(const float* __restrict__ b2,
                                                     const float* __restrict__ bvec,
                                                     float* __restrict__ outp) {
    extern __shared__ __align__(16) char sm[];
    float(*zcol)[8] = (float(*)[8])sm;           // [256][8]    8192 @0
    u64(*psum)[13] = (u64(*)[13])(sm + 8192);    // [512][13]  53248 @8192
    float(*hcol)[8] = (float(*)[8])(sm + 8192);  // alias over psum
    float* bvs = (float*)(sm + 61440);           // 512
    u64* bps = (u64*)(sm + 61952);               // 1024 -> 62976

    const int t = threadIdx.x;
    const int r0 = blockIdx.x * 8;
    float* const zoutp = outp;
    float* const out0p = outp + 1024 * 256;

    const int kg = t >> 7;    // 0..3
    const int cgz = t & 127;  // 0..127

    if (t < 128) {
        bvs[t] = bvec[t];
        bps[t] = *(const u64*)&g_biasproj[2 * t];
    }

    u64 ad[4], ax[4], rd[4];

    // ---- phase A: out = h2 rows @ W2T + b2 (K=1024, 4 chunks) ----
#pragma unroll
    for (int rp = 0; rp < 4; rp++) ad[rp] = ax[rp] = 0ull;

    for (int kc = 0; kc < 1024; kc += 256) {
        __syncthreads();
#pragma unroll
        for (int jj = 0; jj < 4; jj++) {
            int idx = t + 512 * jj;
            int k = idx & 255, r = idx >> 8;
            hcol[k][r] = g_h2[(r0 + r) * 1024 + kc + k];
        }
        __syncthreads();
        mac64_z(ad, ax, g_W2T + (kc + kg * 64) * 256 + 2 * cgz, hcol, kg * 64);
    }
    __syncthreads();  // hcol reads done before psum overwrite
#pragma unroll
    for (int rp = 0; rp < 4; rp++) {
        psum[t][rp * 2 + 0] = ad[rp];
        psum[t][rp * 2 + 1] = ax[rp];
    }
    __syncthreads();
    // combine (1024 units, 2/thread): + b2, no relu, write zcol + out
#pragma unroll
    for (int uu = 0; uu < 2; uu++) {
        int u = t * 2 + uu;
        int cg2 = u >> 3, j = u & 7;
        int rp = j >> 1, dx = j & 1;
        u64 s = psum[cg2][j];
        ADD2(s, psum[128 + cg2][j]);
        ADD2(s, psum[256 + cg2][j]);
        ADD2(s, psum[384 + cg2][j]);
        int c = 2 * cg2;
        u64 bb = *(const u64*)&b2[c];
        if (dx) bb = swp(bb);
        ADD2(s, bb);
        float2 v = unpack2(s);
        int cL = c + dx, cH = c + 1 - dx;
        int re = 2 * rp, ro = 2 * rp + 1;
        zcol[cL][re] = v.x;
        zcol[cH][ro] = v.y;
        out0p[(r0 + re) * 256 + cL] = v.x;
        out0p[(r0 + ro) * 256 + cH] = v.y;
    }
    __syncthreads();

    // ---- 20 merged passes: z-update + previous-z residual, 2 syncs each ----
    const float* const wzptr = g_WzT + (kg * 64) * 256 + 2 * cgz;
    const float* const aaptr = g_AT + (kg * 64) * 128 + cgz;

    for (int p = 0; p < 20; p++) {
#pragma unroll
        for (int rp = 0; rp < 4; rp++) ad[rp] = ax[rp] = rd[rp] = 0ull;
        mac64_merged(ad, ax, rd, wzptr, aaptr, zcol, kg * 64);
#pragma unroll
        for (int rp = 0; rp < 4; rp++) {
            psum[t][rp * 2 + 0] = ad[rp];
            psum[t][rp * 2 + 1] = ax[rp];
            psum[t][8 + rp] = rd[rp];
        }
        __syncthreads();  // (1) psum ready
        // z combine: 2 units/thread, bias_proj + projection, write new zcol
#pragma unroll
        for (int uu = 0; uu < 2; uu++) {
            int u = t * 2 + uu;
            int cg2 = u >> 3, j = u & 7;
            int rp = j >> 1, dx = j & 1;
            u64 s = psum[cg2][j];
            ADD2(s, psum[128 + cg2][j]);
            ADD2(s, psum[256 + cg2][j]);
            ADD2(s, psum[384 + cg2][j]);
            u64 bb = bps[cg2];
            if (dx) bb = swp(bb);
            ADD2(s, bb);
            float2 v = unpack2(s);
            if (cg2 >= 32) {  // cols >= 64 -> relu
                v.x = fmaxf(v.x, 0.f);
                v.y = fmaxf(v.y, 0.f);
            }
            int c = 2 * cg2;
            zcol[c + dx][2 * rp] = v.x;
            zcol[c + 1 - dx][2 * rp + 1] = v.y;
        }
        // res combine (residual of z_p, valid for p>=1): 1 unit/thread
        {
            int cgA = t >> 2, rp = t & 3;
            u64 s = psum[cgA][8 + rp];
            ADD2(s, psum[128 + cgA][8 + rp]);
            ADD2(s, psum[256 + cgA][8 + rp]);
            ADD2(s, psum[384 + cgA][8 + rp]);
            float2 v = unpack2(s);
            float bv = bvs[cgA];
            float m = fmaxf(fabsf(v.x - bv), fabsf(v.y - bv));
#pragma unroll
            for (int o = 16; o; o >>= 1)
                m = fmaxf(m, __shfl_xor_sync(~0u, m, o));
            if (p > 0 && (t & 31) == 0)
                atomicMax(&g_res_arr[p - 1], __float_as_uint(m));
        }
        __syncthreads();  // (2) zcol ready, psum reads done
    }

    // ---- final residual: z_20 @ A -> slot 19 ----
#pragma unroll
    for (int rp = 0; rp < 4; rp++) rd[rp] = 0ull;
#pragma unroll 8
    for (int kk = 0; kk < 64; kk++) {
        int k = kg * 64 + kk;
        u64x2 za = *(const u64x2*)&zcol[k][0];
        u64x2 zb = *(const u64x2*)&zcol[k][4];
        u64 zp[4] = {za.x, za.y, zb.x, zb.y};
        float a = aaptr[kk * 128];
        u64 ap = pack2(a, a);
#pragma unroll
        for (int rp = 0; rp < 4; rp++) FFMA2(rd[rp], zp[rp], ap);
    }
#pragma unroll
    for (int rp = 0; rp < 4; rp++) psum[t][8 + rp] = rd[rp];
    __syncthreads();
    {
        int cgA = t >> 2, rp = t & 3;
        u64 s = psum[cgA][8 + rp];
        ADD2(s, psum[128 + cgA][8 + rp]);
        ADD2(s, psum[256 + cgA][8 + rp]);
        ADD2(s, psum[384 + cgA][8 + rp]);
        float2 v = unpack2(s);
        float bv = bvs[cgA];
        float m = fmaxf(fabsf(v.x - bv), fabsf(v.y - bv));
#pragma unroll
        for (int o = 16; o; o >>= 1) m = fmaxf(m, __shfl_xor_sync(~0u, m, o));
        if ((t & 31) == 0) atomicMax(&g_res_arr[19], __float_as_uint(m));
    }

    // write z_star directly to d_out
#pragma unroll
    for (int jj = 0; jj < 4; jj++) {
        int idx = t + 512 * jj;
        int c = idx & 255, r = idx >> 8;
        zoutp[(r0 + r) * 256 + c] = zcol[c][r];
    }
    __syncthreads();
    __threadfence();
    if (t == 0) {
        if (atomicAdd(&g_solver_done, 1u) == NBLK - 1) {
            int it = 21;
            for (int tt = 0; tt < 20; tt++) {
                unsigned rb = atomicAdd(&g_res_arr[tt], 0u);
                if (__uint_as_float(rb) <= F_TOL_F) {
                    it = tt + 2;
                    break;
                }
            }
            outp[2 * 1024 * 256] = (float)it;
        }
    }
}

// ---------------- launch ------------------------------------------------------
extern "C" void kernel_launch(void* const* d_in, const int* in_sizes, int n_in,
                              void* d_out, int out_size) {
    const float* b_primal = (const float*)d_in[0];
    const float* W0 = (const float*)d_in[1];
    const float* b0 = (const float*)d_in[2];
    const float* W1 = (const float*)d_in[3];
    const float* b1 = (const float*)d_in[4];
    const float* W2 = (const float*)d_in[5];
    const float* b2 = (const float*)d_in[6];
    const float* Amat = (const float*)d_in[7];
    const float* b_vec = (const float*)d_in[8];
    const float* WzProj = (const float*)d_in[9];
    const float* WbProj = (const float*)d_in[10];

    float *h1, *h2;
    cudaGetSymbolAddress((void**)&h1, g_h1);
    cudaGetSymbolAddress((void**)&h2, g_h2);

    static int smem_set = 0;
    if (!smem_set) {
        cudaFuncSetAttribute(solver_kernel,
                             cudaFuncAttributeMaxDynamicSharedMemorySize,
                             SOLVER_SMEM);
        smem_set = 1;
    }

    prep_kernel<<<353, 1024>>>(W2, WzProj, Amat, b_vec, WbProj);

    // h1 = relu(b_primal @ W0^T + b0)   M=1024 N=1024 K=512
    gemm_relu_f2<<<dim3(16, 8), 256>>>(b_primal, W0, b0, h1, 1024, 1024, 512);
    // h2 = relu(h1 @ W1^T + b1)         M=1024 N=1024 K=1024
    gemm_relu_f2<<<dim3(16, 8), 256>>>(h1, W1, b1, h2, 1024, 1024, 1024);

    // fused: out + 20 merged fixed-point passes, writes d_out directly
    solver_kernel<<<NBLK, 512, SOLVER_SMEM>>>(b2, b_vec, (float*)d_out);
}